// round 12
// baseline (speedup 1.0000x reference)
#include <cuda_runtime.h>
#include <cuda_bf16.h>
#include <cstdint>

#define NN 50000
#define NE 800000
#define NF 96
#define NC 40

#define SCAN_TB 256
#define SCAN_BLOCKS ((NN + SCAN_TB - 1) / SCAN_TB)   // 196

#define BUILD_GRID 592     // 4 blocks/SM on 148 SMs -> all resident
#define BUILD_TB   256

#define PROP_GRID  888     // 6 blocks/SM on 148 SMs -> all resident
#define PROP_TB    256

// ---------------- flat static device scratch ----------------
#define OFF_DEG      0
#define OFF_DINV     (OFF_DEG + NN)
#define OFF_COUNTS   (OFF_DINV + NN)
#define OFF_CURSOR   (OFF_COUNTS + NN)
#define OFF_OFFSETS  (OFF_CURSOR + NN)              // NN+1 ints
#define OFF_FLAGS    (OFF_OFFSETS + NN + 8)         // 4 ints
#define OFF_BSUM     (OFF_FLAGS + 8)                // 256 ints
#define OFF_PAIR_SGC (OFF_BSUM + 256)               // NE int2 (src, norm)
#define OFF_PAIR_LPA (OFF_PAIR_SGC + 2 * NE)        // NE int2 (src, ew)
#define OFF_Z0       (OFF_PAIR_LPA + 2 * NE)        // NN*NC
#define OFF_Z1       (OFF_Z0 + NN * NC)
#define OFF_L0       (OFF_Z1 + NN * NC)
#define OFF_L1       (OFF_L0 + NN * NC)
#define SCRATCH_ELEMS (OFF_L1 + NN * NC + 64)

__device__ __align__(256) float g_scratch[SCRATCH_ELEMS];

// Grid-barrier counters: zero-initialized, NEVER reset (monotonic epochs ->
// correct across graph replays). ids 0-3: build, 4-5: props.
__device__ int g_barriers[8];

__device__ __forceinline__ void grid_barrier(int id) {
    __syncthreads();
    if (threadIdx.x == 0) {
        __threadfence();
        int old = atomicAdd(&g_barriers[id], 1);
        int target = (old / (int)gridDim.x + 1) * (int)gridDim.x;
        while (atomicAdd(&g_barriers[id], 0) < target) { __nanosleep(200); }
        __threadfence();
    }
    __syncthreads();
}

// flags[0]: edge_index is int64; flags[1]: mask is 4-byte; flags[2]: y is int64
__device__ __forceinline__ int load_idx(const void* p, long long i, int is64) {
    return is64 ? (int)((const long long*)p)[i] : ((const int*)p)[i];
}

// ================== build kernel (CSR only; gemm moved out) ==================
__global__ __launch_bounds__(BUILD_TB, 4)
void build_kernel(float* __restrict__ deg, int* __restrict__ counts,
                  int* __restrict__ flags, int* __restrict__ bsum,
                  int* __restrict__ offsets, int* __restrict__ cursor,
                  float* __restrict__ dinv,
                  int2* __restrict__ ps, int2* __restrict__ pl,
                  float* __restrict__ l0,
                  const void* __restrict__ ei, const void* __restrict__ y,
                  const void* __restrict__ mask,
                  const float* __restrict__ ew) {
    __shared__ int sh_pool[2 * SCAN_TB];
    const int tid = threadIdx.x;
    const int gsz = gridDim.x * blockDim.x;
    const int gtid = blockIdx.x * blockDim.x + tid;

    // P0: init + sniff
    for (int i = gtid; i < NN; i += gsz) { deg[i] = 1.0f; counts[i] = 0; }
    if (blockIdx.x == 0) {
        __shared__ int narrow[3];
        if (tid < 3) narrow[tid] = 0;
        __syncthreads();
        const int* ei32 = (const int*)ei;
        const int* y32  = (const int*)y;
        const unsigned char* m8 = (const unsigned char*)mask;
        if (ei32[2 * tid + 1] != 0) narrow[0] = 1;
        if (y32[2 * tid + 1]  != 0) narrow[2] = 1;
        for (int t = tid; t < 4096; t += 256)
            if ((t & 3) != 0 && m8[t] != 0) narrow[1] = 1;
        __syncthreads();
        if (tid < 3) flags[tid] = narrow[tid] ? 0 : 1;
    }
    grid_barrier(0);

    // P1: degree/count atomics
    {
        int is64 = flags[0];
        for (int e = gtid; e < NE; e += gsz) {
            int c = load_idx(ei, (long long)NE + e, is64);
            if ((unsigned)c < NN) {
                atomicAdd(&deg[c], ew[e]);
                atomicAdd(&counts[c], 1);
            }
        }
    }
    grid_barrier(1);

    // P2: chunk reduce + dinv
    {
        int* sh = sh_pool;
        if (blockIdx.x < SCAN_BLOCKS) {
            int i = blockIdx.x * SCAN_TB + tid;
            sh[tid] = (i < NN) ? counts[i] : 0;
            __syncthreads();
            for (int off = SCAN_TB / 2; off > 0; off >>= 1) {
                if (tid < off) sh[tid] += sh[tid + off];
                __syncthreads();
            }
            if (tid == 0) bsum[blockIdx.x] = sh[0];
        }
        for (int i = gtid; i < NN; i += gsz) dinv[i] = rsqrtf(deg[i]);
    }
    grid_barrier(2);

    // P3: scan -> offsets, cursor
    if (blockIdx.x < SCAN_BLOCKS) {
        int* sb = sh_pool;
        int* sh = sb + SCAN_TB;
        int bv = (tid < SCAN_BLOCKS) ? bsum[tid] : 0;
        sb[tid] = bv;
        __syncthreads();
        for (int off = 1; off < SCAN_TB; off <<= 1) {
            int u = (tid >= off) ? sb[tid - off] : 0;
            __syncthreads();
            sb[tid] += u;
            __syncthreads();
        }
        int blockPrefix = (blockIdx.x == 0) ? 0 : sb[blockIdx.x - 1];
        if (blockIdx.x == 0 && tid == 0) offsets[NN] = sb[SCAN_BLOCKS - 1];

        int i = blockIdx.x * SCAN_TB + tid;
        int v = (i < NN) ? counts[i] : 0;
        sh[tid] = v;
        __syncthreads();
        for (int off = 1; off < SCAN_TB; off <<= 1) {
            int u = (tid >= off) ? sh[tid - off] : 0;
            __syncthreads();
            sh[tid] += u;
            __syncthreads();
        }
        if (i < NN) {
            int excl = blockPrefix + sh[tid] - v;
            offsets[i] = excl;
            cursor[i]  = excl;
        }
    }
    grid_barrier(3);

    // P4: fill CSR + LPA one-hot init
    {
        int is64 = flags[0];
        for (int e = gtid; e < NE; e += gsz) {
            int r = load_idx(ei, e, is64);
            int c = load_idx(ei, (long long)NE + e, is64);
            if ((unsigned)r < NN && (unsigned)c < NN) {
                int pos = atomicAdd(&cursor[c], 1);
                if ((unsigned)pos < NE) {
                    float w = ew[e];
                    ps[pos] = make_int2(r, __float_as_int(dinv[r] * w * dinv[c]));
                    pl[pos] = make_int2(r, __float_as_int(w));
                }
            }
        }
        int m4  = flags[1];
        int y64 = flags[2];
        for (int idx = gtid; idx < NN * NC; idx += gsz) {
            int n = idx / NC, c = idx % NC;
            int yv = load_idx(y, n, y64);
            int mv = m4 ? ((const int*)mask)[n]
                        : (int)((const unsigned char*)mask)[n];
            l0[idx] = (mv != 0 && yv == c) ? 1.0f : 0.0f;
        }
    }
}

// ---------------- 40-wide propagate (exact R11 body) ----------
template <bool SELF, bool BIAS>
__device__ __forceinline__ void prop40(int n, int lane,
                                       const float* __restrict__ in,
                                       float* __restrict__ out,
                                       const float* __restrict__ dinv,
                                       const float* __restrict__ bias,
                                       const int* __restrict__ offsets,
                                       const int2* __restrict__ pr) {
    int grp = lane / 10;
    int sub = lane - grp * 10;
    bool active = (lane < 30);
    float4 acc = make_float4(0.f, 0.f, 0.f, 0.f);
    int beg = offsets[n], end = offsets[n + 1];
    int e = beg;
    for (; e + 6 <= end; e += 6) {
        int2 pa, pb;
        float wa = 0.f, wb = 0.f; int sa = 0, sb = 0;
        if (active) {
            pa = pr[e + grp];     sa = pa.x; wa = __int_as_float(pa.y);
            pb = pr[e + 3 + grp]; sb = pb.x; wb = __int_as_float(pb.y);
        }
        float4 va = make_float4(0.f,0.f,0.f,0.f), vb = va;
        if (wa != 0.f) va = ((const float4*)(in + (size_t)sa * NC))[sub];
        if (wb != 0.f) vb = ((const float4*)(in + (size_t)sb * NC))[sub];
        acc.x += wa * va.x + wb * vb.x;
        acc.y += wa * va.y + wb * vb.y;
        acc.z += wa * va.z + wb * vb.z;
        acc.w += wa * va.w + wb * vb.w;
    }
    for (; e < end; e += 3) {
        int idx = e + grp;
        float w = 0.f; int s = 0;
        if (active && idx < end) {
            int2 p = pr[idx]; s = p.x; w = __int_as_float(p.y);
        }
        if (w != 0.f) {
            float4 v = ((const float4*)(in + (size_t)s * NC))[sub];
            acc.x += w * v.x; acc.y += w * v.y; acc.z += w * v.z; acc.w += w * v.w;
        }
    }
    unsigned m = 0xFFFFFFFFu;
    float t1, t2;
    t1 = __shfl_sync(m, acc.x, lane + 10); t2 = __shfl_sync(m, acc.x, lane + 20);
    acc.x += t1 + t2;
    t1 = __shfl_sync(m, acc.y, lane + 10); t2 = __shfl_sync(m, acc.y, lane + 20);
    acc.y += t1 + t2;
    t1 = __shfl_sync(m, acc.z, lane + 10); t2 = __shfl_sync(m, acc.z, lane + 20);
    acc.z += t1 + t2;
    t1 = __shfl_sync(m, acc.w, lane + 10); t2 = __shfl_sync(m, acc.w, lane + 20);
    acc.w += t1 + t2;

    if (lane < 10) {
        if (SELF) {
            float dii = dinv[n]; dii *= dii;
            float4 v = ((const float4*)(in + (size_t)n * NC))[lane];
            acc.x += dii * v.x; acc.y += dii * v.y;
            acc.z += dii * v.z; acc.w += dii * v.w;
        }
        if (BIAS) {
            float4 bb = ((const float4*)bias)[lane];
            acc.x += bb.x; acc.y += bb.y; acc.z += bb.z; acc.w += bb.w;
        }
        ((float4*)(out + (size_t)n * NC))[lane] = acc;
    }
}

// ================== fused persistent props kernel ==================
// Phase A: gemm (z0 = x@W) || LPA iter1 (l0 -> l1)
// Phase B: SGC hop1 (z0 -> z1) || LPA iter2 (l1 -> l0)
// Phase C: SGC hop2 +bias (z1 -> x_out) || LPA iter3 (l0 -> lpa_out)
#define GEMM_ROWS 16
#define GEMM_TILES (NN / GEMM_ROWS)        // 3125
#define LPA_BLKS   ((NN + 7) / 8)          // 6250 node-blocks (8 warps each)
#define TASKS_A    (GEMM_TILES + LPA_BLKS) // 9375: t%3==0 -> gemm, else lpa
#define TASKS_BC   (2 * LPA_BLKS)          // 12500: parity roles

__global__ __launch_bounds__(PROP_TB, 6)
void props_kernel(const float* __restrict__ x, const float* __restrict__ W,
                  const float* __restrict__ bias,
                  float* __restrict__ z0, float* __restrict__ z1,
                  float* __restrict__ l0, float* __restrict__ l1,
                  float* __restrict__ x_out, float* __restrict__ lpa_out,
                  const float* __restrict__ dinv,
                  const int* __restrict__ offsets,
                  const int2* __restrict__ ps, const int2* __restrict__ pl) {
    __shared__ float sW[NF * NC];           // 15360 B
    __shared__ float sH[GEMM_ROWS * NF];    //  6144 B
    const int tid = threadIdx.x;
    const int lane = tid & 31;
    const int wib  = tid >> 5;

    // ---- Phase A ----
    for (int i = tid; i < NF * NC; i += PROP_TB) sW[i] = W[i];
    __syncthreads();
    for (int t = blockIdx.x; t < TASKS_A; t += gridDim.x) {
        if (t % 3 == 0) {
            int row0 = (t / 3) * GEMM_ROWS;
            const float* hp = x + (size_t)row0 * NF;
            __syncthreads();
            for (int i = tid; i < GEMM_ROWS * NF; i += PROP_TB) sH[i] = hp[i];
            __syncthreads();
            for (int o = tid; o < GEMM_ROWS * NC; o += PROP_TB) {
                int r = o / NC, c = o % NC;
                float acc = 0.0f;
                const float* hr = &sH[r * NF];
                #pragma unroll 8
                for (int k = 0; k < NF; k++) acc += hr[k] * sW[k * NC + c];
                z0[(size_t)(row0 + r) * NC + c] = acc;
            }
        } else {
            int blk = t - t / 3 - 1;       // 0..LPA_BLKS-1
            int n = blk * 8 + wib;
            if (n < NN)
                prop40<false, false>(n, lane, l0, l1, dinv, bias, offsets, pl);
        }
    }
    grid_barrier(4);

    // ---- Phase B ----
    for (int t = blockIdx.x; t < TASKS_BC; t += gridDim.x) {
        int n = (t >> 1) * 8 + wib;
        if (n >= NN) continue;
        if ((t & 1) == 0)
            prop40<true, false>(n, lane, z0, z1, dinv, bias, offsets, ps);
        else
            prop40<false, false>(n, lane, l1, l0, dinv, bias, offsets, pl);
    }
    grid_barrier(5);

    // ---- Phase C ----
    for (int t = blockIdx.x; t < TASKS_BC; t += gridDim.x) {
        int n = (t >> 1) * 8 + wib;
        if (n >= NN) continue;
        if ((t & 1) == 0)
            prop40<true, true>(n, lane, z1, x_out, dinv, bias, offsets, ps);
        else
            prop40<false, false>(n, lane, l0, lpa_out, dinv, bias, offsets, pl);
    }
}

// ---------------- launch ----------------

extern "C" void kernel_launch(void* const* d_in, const int* in_sizes, int n_in,
                              void* d_out, int out_size) {
    const float* x    = (const float*)d_in[0];
    const void*  ei   = d_in[1];
    const void*  y    = d_in[2];
    const void*  mask = d_in[3];
    const float* ew   = (const float*)d_in[4];
    const float* W    = (const float*)d_in[5];
    const float* b    = (const float*)d_in[6];
    float* out = (float*)d_out;
    float* x_out   = out;
    float* lpa_out = out + NN * NC;

    static float* s = nullptr;
    if (s == nullptr) {
        void* p = nullptr;
        cudaGetSymbolAddress(&p, g_scratch);
        s = (float*)p;
    }
    float* deg     = s + OFF_DEG;
    float* dinv    = s + OFF_DINV;
    int*   counts  = (int*)(s + OFF_COUNTS);
    int*   cursor  = (int*)(s + OFF_CURSOR);
    int*   offsets = (int*)(s + OFF_OFFSETS);
    int*   flags   = (int*)(s + OFF_FLAGS);
    int*   bsum    = (int*)(s + OFF_BSUM);
    int2*  ps      = (int2*)(s + OFF_PAIR_SGC);
    int2*  pl      = (int2*)(s + OFF_PAIR_LPA);
    float* z0      = s + OFF_Z0;
    float* z1      = s + OFF_Z1;
    float* l0      = s + OFF_L0;
    float* l1      = s + OFF_L1;

    // K0: CSR build (device grid barriers)
    build_kernel<<<BUILD_GRID, BUILD_TB>>>(
        deg, counts, flags, bsum, offsets, cursor, dinv,
        ps, pl, l0, ei, y, mask, ew);

    // K1: gemm + 5 propagate passes, fully fused (persistent, grid barriers)
    props_kernel<<<PROP_GRID, PROP_TB>>>(
        x, W, b, z0, z1, l0, l1, x_out, lpa_out, dinv, offsets, ps, pl);

    (void)in_sizes; (void)n_in; (void)out_size;
}

// round 13
// speedup vs baseline: 1.1766x; 1.1766x over previous
#include <cuda_runtime.h>
#include <cuda_bf16.h>
#include <cstdint>

#define NN 50000
#define NE 800000
#define NF 96
#define NC 40

#define SCAN_TB 256
#define SCAN_BLOCKS ((NN + SCAN_TB - 1) / SCAN_TB)   // 196

#define BUILD_GRID 592     // 4 blocks/SM on 148 SMs -> all resident
#define BUILD_TB   256
#define GEMM_SPLIT 192     // blocks [0,192) gemm, [192,592) deg_count in P1

// ---------------- flat static device scratch ----------------
#define OFF_DEG      0
#define OFF_DINV     (OFF_DEG + NN)
#define OFF_COUNTS   (OFF_DINV + NN)
#define OFF_CURSOR   (OFF_COUNTS + NN)
#define OFF_OFFSETS  (OFF_CURSOR + NN)              // NN+1 ints
#define OFF_FLAGS    (OFF_OFFSETS + NN + 8)         // 4 ints
#define OFF_BSUM     (OFF_FLAGS + 8)                // 256 ints
#define OFF_PAIR_SGC (OFF_BSUM + 256)               // NE int2 (src, norm)
#define OFF_PAIR_LPA (OFF_PAIR_SGC + 2 * NE)        // NE int2 (src, ew)
#define OFF_Z0       (OFF_PAIR_LPA + 2 * NE)        // NN*NC
#define OFF_Z1       (OFF_Z0 + NN * NC)
#define OFF_L0       (OFF_Z1 + NN * NC)
#define OFF_L1       (OFF_L0 + NN * NC)
#define SCRATCH_ELEMS (OFF_L1 + NN * NC + 64)

__device__ __align__(256) float g_scratch[SCRATCH_ELEMS];

// Grid-barrier counters: zero-initialized, NEVER reset (monotonic epochs ->
// correct across graph replays).
__device__ int g_barriers[8];

__device__ __forceinline__ void grid_barrier(int id) {
    __syncthreads();
    if (threadIdx.x == 0) {
        __threadfence();
        int old = atomicAdd(&g_barriers[id], 1);
        int target = (old / (int)gridDim.x + 1) * (int)gridDim.x;
        while (atomicAdd(&g_barriers[id], 0) < target) { __nanosleep(200); }
        __threadfence();
    }
    __syncthreads();
}

// flags[0]: edge_index is int64; flags[1]: mask is 4-byte; flags[2]: y is int64
__device__ __forceinline__ int load_idx(const void* p, long long i, int is64) {
    return is64 ? (int)((const long long*)p)[i] : ((const int*)p)[i];
}

#define GEMM_ROWS 32
#define GEMM_TILES ((NN + GEMM_ROWS - 1) / GEMM_ROWS)   // 1563

// ================== ONE fused build kernel ==================
// P0: init deg/counts + sniff
// P1: gemm (blocks 0..191) || deg_count atomics (blocks 192..591)
// P2: per-chunk reduce of counts -> bsum; dinv
// P3: redundant bsum scan + local scan -> offsets, cursor
// P4: fill CSR pairs + LPA one-hot init
__global__ __launch_bounds__(BUILD_TB, 4)
void build_kernel(float* __restrict__ deg, int* __restrict__ counts,
                  int* __restrict__ flags, int* __restrict__ bsum,
                  int* __restrict__ offsets, int* __restrict__ cursor,
                  float* __restrict__ dinv,
                  int2* __restrict__ ps, int2* __restrict__ pl,
                  float* __restrict__ z, float* __restrict__ l0,
                  const void* __restrict__ ei, const void* __restrict__ y,
                  const void* __restrict__ mask,
                  const float* __restrict__ ew,
                  const float* __restrict__ x, const float* __restrict__ W) {
    __shared__ __align__(16) char sh_pool[(NF * NC + GEMM_ROWS * NF) * 4]; // 27648 B
    const int tid = threadIdx.x;
    const int gsz = gridDim.x * blockDim.x;
    const int gtid = blockIdx.x * blockDim.x + tid;

    // ---------------- P0: init + sniff ----------------
    for (int i = gtid; i < NN; i += gsz) { deg[i] = 1.0f; counts[i] = 0; }
    if (blockIdx.x == 0) {
        __shared__ int narrow[3];
        if (tid < 3) narrow[tid] = 0;
        __syncthreads();
        const int* ei32 = (const int*)ei;
        const int* y32  = (const int*)y;
        const unsigned char* m8 = (const unsigned char*)mask;
        if (ei32[2 * tid + 1] != 0) narrow[0] = 1;
        if (y32[2 * tid + 1]  != 0) narrow[2] = 1;
        for (int t = tid; t < 4096; t += 256)
            if ((t & 3) != 0 && m8[t] != 0) narrow[1] = 1;
        __syncthreads();
        if (tid < 3) flags[tid] = narrow[tid] ? 0 : 1;
    }
    grid_barrier(0);

    // ---------------- P1: gemm || deg_count ----------------
    if (blockIdx.x < GEMM_SPLIT) {
        // gemm: z = x @ W (fma-pipe) — overlaps the atomic-bound deg_count
        float* sW = (float*)sh_pool;
        float* sH = sW + NF * NC;
        for (int i = tid; i < NF * NC; i += BUILD_TB) sW[i] = W[i];
        for (int tile = blockIdx.x; tile < GEMM_TILES; tile += GEMM_SPLIT) {
            int row0 = tile * GEMM_ROWS;
            int nrows = min(GEMM_ROWS, NN - row0);
            int nelem = nrows * NF;
            const float* hp = x + (size_t)row0 * NF;
            __syncthreads();
            for (int i = tid; i < nelem; i += BUILD_TB) sH[i] = hp[i];
            __syncthreads();
            int nout = nrows * NC;
            for (int o = tid; o < nout; o += BUILD_TB) {
                int r = o / NC, c = o % NC;
                float acc = 0.0f;
                const float* hr = &sH[r * NF];
                #pragma unroll 8
                for (int k = 0; k < NF; k++) acc += hr[k] * sW[k * NC + c];
                z[(size_t)(row0 + r) * NC + c] = acc;
            }
        }
    } else {
        int is64 = flags[0];
        const int nblk = BUILD_GRID - GEMM_SPLIT;        // 400
        const int lsz  = nblk * BUILD_TB;
        int e0 = (blockIdx.x - GEMM_SPLIT) * BUILD_TB + tid;
        for (int e = e0; e < NE; e += lsz) {
            int c = load_idx(ei, (long long)NE + e, is64);
            if ((unsigned)c < NN) {
                atomicAdd(&deg[c], ew[e]);
                atomicAdd(&counts[c], 1);
            }
        }
    }
    grid_barrier(1);

    // ---------------- P2: chunk reduce + dinv ----------------
    {
        int* sh = (int*)sh_pool;
        if (blockIdx.x < SCAN_BLOCKS) {
            int i = blockIdx.x * SCAN_TB + tid;
            sh[tid] = (i < NN) ? counts[i] : 0;
            __syncthreads();
            for (int off = SCAN_TB / 2; off > 0; off >>= 1) {
                if (tid < off) sh[tid] += sh[tid + off];
                __syncthreads();
            }
            if (tid == 0) bsum[blockIdx.x] = sh[0];
        }
        for (int i = gtid; i < NN; i += gsz) dinv[i] = rsqrtf(deg[i]);
    }
    grid_barrier(2);

    // ---------------- P3: scan -> offsets, cursor ----------------
    if (blockIdx.x < SCAN_BLOCKS) {
        int* sb = (int*)sh_pool;
        int* sh = sb + SCAN_TB;
        int bv = (tid < SCAN_BLOCKS) ? bsum[tid] : 0;
        sb[tid] = bv;
        __syncthreads();
        for (int off = 1; off < SCAN_TB; off <<= 1) {
            int u = (tid >= off) ? sb[tid - off] : 0;
            __syncthreads();
            sb[tid] += u;
            __syncthreads();
        }
        int blockPrefix = (blockIdx.x == 0) ? 0 : sb[blockIdx.x - 1];
        if (blockIdx.x == 0 && tid == 0) offsets[NN] = sb[SCAN_BLOCKS - 1];

        int i = blockIdx.x * SCAN_TB + tid;
        int v = (i < NN) ? counts[i] : 0;
        sh[tid] = v;
        __syncthreads();
        for (int off = 1; off < SCAN_TB; off <<= 1) {
            int u = (tid >= off) ? sh[tid - off] : 0;
            __syncthreads();
            sh[tid] += u;
            __syncthreads();
        }
        if (i < NN) {
            int excl = blockPrefix + sh[tid] - v;
            offsets[i] = excl;
            cursor[i]  = excl;
        }
    }
    grid_barrier(3);

    // ---------------- P4: fill CSR + LPA one-hot init ----------------
    {
        int is64 = flags[0];
        for (int e = gtid; e < NE; e += gsz) {
            int r = load_idx(ei, e, is64);
            int c = load_idx(ei, (long long)NE + e, is64);
            if ((unsigned)r < NN && (unsigned)c < NN) {
                int pos = atomicAdd(&cursor[c], 1);
                if ((unsigned)pos < NE) {
                    float w = ew[e];
                    ps[pos] = make_int2(r, __float_as_int(dinv[r] * w * dinv[c]));
                    pl[pos] = make_int2(r, __float_as_int(w));
                }
            }
        }
        int m4  = flags[1];
        int y64 = flags[2];
        for (int idx = gtid; idx < NN * NC; idx += gsz) {
            int n = idx / NC, c = idx % NC;
            int yv = load_idx(y, n, y64);
            int mv = m4 ? ((const int*)mask)[n]
                        : (int)((const unsigned char*)mask)[n];
            l0[idx] = (mv != 0 && yv == c) ? 1.0f : 0.0f;
        }
    }
}

// ---------------- 40-wide propagate (exact R10/R11 body) ----------
template <bool SELF, bool BIAS>
__device__ __forceinline__ void prop40(int n, int lane,
                                       const float* __restrict__ in,
                                       float* __restrict__ out,
                                       const float* __restrict__ dinv,
                                       const float* __restrict__ bias,
                                       const int* __restrict__ offsets,
                                       const int2* __restrict__ pr) {
    int grp = lane / 10;
    int sub = lane - grp * 10;
    bool active = (lane < 30);
    float4 acc = make_float4(0.f, 0.f, 0.f, 0.f);
    int beg = offsets[n], end = offsets[n + 1];
    int e = beg;
    for (; e + 6 <= end; e += 6) {
        int2 pa, pb;
        float wa = 0.f, wb = 0.f; int sa = 0, sb = 0;
        if (active) {
            pa = pr[e + grp];     sa = pa.x; wa = __int_as_float(pa.y);
            pb = pr[e + 3 + grp]; sb = pb.x; wb = __int_as_float(pb.y);
        }
        float4 va = make_float4(0.f,0.f,0.f,0.f), vb = va;
        if (wa != 0.f) va = ((const float4*)(in + (size_t)sa * NC))[sub];
        if (wb != 0.f) vb = ((const float4*)(in + (size_t)sb * NC))[sub];
        acc.x += wa * va.x + wb * vb.x;
        acc.y += wa * va.y + wb * vb.y;
        acc.z += wa * va.z + wb * vb.z;
        acc.w += wa * va.w + wb * vb.w;
    }
    for (; e < end; e += 3) {
        int idx = e + grp;
        float w = 0.f; int s = 0;
        if (active && idx < end) {
            int2 p = pr[idx]; s = p.x; w = __int_as_float(p.y);
        }
        if (w != 0.f) {
            float4 v = ((const float4*)(in + (size_t)s * NC))[sub];
            acc.x += w * v.x; acc.y += w * v.y; acc.z += w * v.z; acc.w += w * v.w;
        }
    }
    unsigned m = 0xFFFFFFFFu;
    float t1, t2;
    t1 = __shfl_sync(m, acc.x, lane + 10); t2 = __shfl_sync(m, acc.x, lane + 20);
    acc.x += t1 + t2;
    t1 = __shfl_sync(m, acc.y, lane + 10); t2 = __shfl_sync(m, acc.y, lane + 20);
    acc.y += t1 + t2;
    t1 = __shfl_sync(m, acc.z, lane + 10); t2 = __shfl_sync(m, acc.z, lane + 20);
    acc.z += t1 + t2;
    t1 = __shfl_sync(m, acc.w, lane + 10); t2 = __shfl_sync(m, acc.w, lane + 20);
    acc.w += t1 + t2;

    if (lane < 10) {
        if (SELF) {
            float dii = dinv[n]; dii *= dii;
            float4 v = ((const float4*)(in + (size_t)n * NC))[lane];
            acc.x += dii * v.x; acc.y += dii * v.y;
            acc.z += dii * v.z; acc.w += dii * v.w;
        }
        if (BIAS) {
            float4 bb = ((const float4*)bias)[lane];
            acc.x += bb.x; acc.y += bb.y; acc.z += bb.z; acc.w += bb.w;
        }
        ((float4*)(out + (size_t)n * NC))[lane] = acc;
    }
}

#define PROP_BLOCKS ((NN + 7) / 8)    // 6250 blocks per role

template <bool LAST>
__global__ __launch_bounds__(256) void prop_pair_kernel(
        const float* __restrict__ sgc_in, float* __restrict__ sgc_out,
        const float* __restrict__ lpa_in, float* __restrict__ lpa_out,
        const float* __restrict__ dinv, const float* __restrict__ bias,
        const int* __restrict__ offsets,
        const int2* __restrict__ ps, const int2* __restrict__ pl) {
    int lane = threadIdx.x & 31;
    int wib  = threadIdx.x >> 5;
    int role = blockIdx.x & 1;
    int n = (blockIdx.x >> 1) * 8 + wib;
    if (n >= NN) return;
    if (role == 0) {
        prop40<true, LAST>(n, lane, sgc_in, sgc_out, dinv, bias, offsets, ps);
    } else {
        prop40<false, false>(n, lane, lpa_in, lpa_out, dinv, bias, offsets, pl);
    }
}

__global__ __launch_bounds__(256) void lpa_final_kernel(
        const float* __restrict__ in, float* __restrict__ out,
        const int* __restrict__ offsets, const int2* __restrict__ pl) {
    int lane = threadIdx.x & 31;
    int n = blockIdx.x * 8 + (threadIdx.x >> 5);
    if (n < NN) prop40<false, false>(n, lane, in, out, nullptr, nullptr, offsets, pl);
}

// ---------------- launch ----------------

extern "C" void kernel_launch(void* const* d_in, const int* in_sizes, int n_in,
                              void* d_out, int out_size) {
    const float* x    = (const float*)d_in[0];
    const void*  ei   = d_in[1];
    const void*  y    = d_in[2];
    const void*  mask = d_in[3];
    const float* ew   = (const float*)d_in[4];
    const float* W    = (const float*)d_in[5];
    const float* b    = (const float*)d_in[6];
    float* out = (float*)d_out;
    float* x_out   = out;
    float* lpa_out = out + NN * NC;

    static float* s = nullptr;
    if (s == nullptr) {
        void* p = nullptr;
        cudaGetSymbolAddress(&p, g_scratch);
        s = (float*)p;
    }
    float* deg     = s + OFF_DEG;
    float* dinv    = s + OFF_DINV;
    int*   counts  = (int*)(s + OFF_COUNTS);
    int*   cursor  = (int*)(s + OFF_CURSOR);
    int*   offsets = (int*)(s + OFF_OFFSETS);
    int*   flags   = (int*)(s + OFF_FLAGS);
    int*   bsum    = (int*)(s + OFF_BSUM);
    int2*  ps      = (int2*)(s + OFF_PAIR_SGC);
    int2*  pl      = (int2*)(s + OFF_PAIR_LPA);
    float* z0      = s + OFF_Z0;
    float* z1      = s + OFF_Z1;
    float* l0      = s + OFF_L0;
    float* l1      = s + OFF_L1;

    // K0: CSR build + sniff + gemm (gemm overlapped with deg_count in P1)
    build_kernel<<<BUILD_GRID, BUILD_TB>>>(
        deg, counts, flags, bsum, offsets, cursor, dinv,
        ps, pl, z0, l0, ei, y, mask, ew, x, W);

    // K1: SGC hop1 + LPA iter1 (parity-interleaved roles)
    prop_pair_kernel<false><<<2 * PROP_BLOCKS, 256>>>(
        z0, z1, l0, l1, dinv, b, offsets, ps, pl);
    // K2: SGC hop2 (+bias -> x_out) + LPA iter2
    prop_pair_kernel<true><<<2 * PROP_BLOCKS, 256>>>(
        z1, x_out, l1, l0, dinv, b, offsets, ps, pl);
    // K3: LPA iter3 -> lpa_out
    lpa_final_kernel<<<PROP_BLOCKS, 256>>>(l0, lpa_out, offsets, pl);

    (void)in_sizes; (void)n_in; (void)out_size;
}

// round 14
// speedup vs baseline: 1.3850x; 1.1771x over previous
#include <cuda_runtime.h>
#include <cuda_bf16.h>
#include <cstdint>

#define NN 50000
#define NE 800000
#define NF 96
#define NC 40

#define SCAN_TB 256
#define SCAN_BLOCKS ((NN + SCAN_TB - 1) / SCAN_TB)   // 196

#define BUILD_GRID 592     // 4 blocks/SM on 148 SMs -> all resident
#define BUILD_TB   256

// ---------------- flat static device scratch ----------------
#define OFF_DEG      0
#define OFF_DINV     (OFF_DEG + NN)
#define OFF_COUNTS   (OFF_DINV + NN)
#define OFF_CURSOR   (OFF_COUNTS + NN)
#define OFF_OFFSETS  (OFF_CURSOR + NN)              // NN+1 ints
#define OFF_FLAGS    (OFF_OFFSETS + NN + 8)         // 4 ints
#define OFF_BSUM     (OFF_FLAGS + 8)                // 256 ints
#define OFF_PAIR_SGC (OFF_BSUM + 256)               // NE int2 (src, norm)
#define OFF_PAIR_LPA (OFF_PAIR_SGC + 2 * NE)        // NE int2 (src, ew)
#define OFF_Z0       (OFF_PAIR_LPA + 2 * NE)        // NN*NC
#define OFF_Z1       (OFF_Z0 + NN * NC)
#define OFF_L0       (OFF_Z1 + NN * NC)
#define OFF_L1       (OFF_L0 + NN * NC)
#define SCRATCH_ELEMS (OFF_L1 + NN * NC + 64)

__device__ __align__(256) float g_scratch[SCRATCH_ELEMS];

// Grid-barrier counters: zero-initialized, NEVER reset (monotonic epochs ->
// correct across graph replays).
__device__ int g_barriers[8];

__device__ __forceinline__ void grid_barrier(int id) {
    __syncthreads();
    if (threadIdx.x == 0) {
        __threadfence();
        int old = atomicAdd(&g_barriers[id], 1);
        int target = (old / (int)gridDim.x + 1) * (int)gridDim.x;
        while (atomicAdd(&g_barriers[id], 0) < target) { __nanosleep(200); }
        __threadfence();
    }
    __syncthreads();
}

// flags[0]: edge_index is int64; flags[1]: mask is 4-byte; flags[2]: y is int64
__device__ __forceinline__ int load_idx(const void* p, long long i, int is64) {
    return is64 ? (int)((const long long*)p)[i] : ((const int*)p)[i];
}

#define GEMM_ROWS 32
#define GEMM_TILES ((NN + GEMM_ROWS - 1) / GEMM_ROWS)   // 1563

// ================== ONE fused build kernel (exact R11 form, minus l0 init) ==
// P0: init deg/counts + sniff (block 0) + gemm z = x@W (grid-stride, all blocks)
// P1: deg_count (atomics)
// P2: per-chunk reduce of counts -> bsum; dinv
// P3: redundant bsum scan + local scan -> offsets, cursor
// P4: fill CSR pairs
__global__ __launch_bounds__(BUILD_TB, 4)
void build_kernel(float* __restrict__ deg, int* __restrict__ counts,
                  int* __restrict__ flags, int* __restrict__ bsum,
                  int* __restrict__ offsets, int* __restrict__ cursor,
                  float* __restrict__ dinv,
                  int2* __restrict__ ps, int2* __restrict__ pl,
                  float* __restrict__ z,
                  const void* __restrict__ ei, const void* __restrict__ y,
                  const void* __restrict__ mask,
                  const float* __restrict__ ew,
                  const float* __restrict__ x, const float* __restrict__ W) {
    __shared__ __align__(16) char sh_pool[(NF * NC + GEMM_ROWS * NF) * 4]; // 27648 B
    const int tid = threadIdx.x;
    const int gsz = gridDim.x * blockDim.x;
    const int gtid = blockIdx.x * blockDim.x + tid;

    // ---------------- P0 ----------------
    for (int i = gtid; i < NN; i += gsz) { deg[i] = 1.0f; counts[i] = 0; }

    if (blockIdx.x == 0) {
        __shared__ int narrow[3];
        if (tid < 3) narrow[tid] = 0;
        __syncthreads();
        const int* ei32 = (const int*)ei;
        const int* y32  = (const int*)y;
        const unsigned char* m8 = (const unsigned char*)mask;
        if (ei32[2 * tid + 1] != 0) narrow[0] = 1;
        if (y32[2 * tid + 1]  != 0) narrow[2] = 1;
        for (int t = tid; t < 4096; t += 256)
            if ((t & 3) != 0 && m8[t] != 0) narrow[1] = 1;
        __syncthreads();
        if (tid < 3) flags[tid] = narrow[tid] ? 0 : 1;
    }

    // gemm: z = x @ W  (each block loads W once, loops over row tiles)
    {
        float* sW = (float*)sh_pool;
        float* sH = sW + NF * NC;
        for (int i = tid; i < NF * NC; i += BUILD_TB) sW[i] = W[i];
        for (int tile = blockIdx.x; tile < GEMM_TILES; tile += gridDim.x) {
            int row0 = tile * GEMM_ROWS;
            int nrows = min(GEMM_ROWS, NN - row0);
            int nelem = nrows * NF;
            const float* hp = x + (size_t)row0 * NF;
            __syncthreads();
            for (int i = tid; i < nelem; i += BUILD_TB) sH[i] = hp[i];
            __syncthreads();
            int nout = nrows * NC;
            for (int o = tid; o < nout; o += BUILD_TB) {
                int r = o / NC, c = o % NC;
                float acc = 0.0f;
                const float* hr = &sH[r * NF];
                #pragma unroll 8
                for (int k = 0; k < NF; k++) acc += hr[k] * sW[k * NC + c];
                z[(size_t)(row0 + r) * NC + c] = acc;
            }
        }
    }
    grid_barrier(0);

    // ---------------- P1: degree/count atomics ----------------
    {
        int is64 = flags[0];
        for (int e = gtid; e < NE; e += gsz) {
            int c = load_idx(ei, (long long)NE + e, is64);
            if ((unsigned)c < NN) {
                atomicAdd(&deg[c], ew[e]);
                atomicAdd(&counts[c], 1);
            }
        }
    }
    grid_barrier(1);

    // ---------------- P2: chunk reduce + dinv ----------------
    {
        int* sh = (int*)sh_pool;
        if (blockIdx.x < SCAN_BLOCKS) {
            int i = blockIdx.x * SCAN_TB + tid;
            sh[tid] = (i < NN) ? counts[i] : 0;
            __syncthreads();
            for (int off = SCAN_TB / 2; off > 0; off >>= 1) {
                if (tid < off) sh[tid] += sh[tid + off];
                __syncthreads();
            }
            if (tid == 0) bsum[blockIdx.x] = sh[0];
        }
        for (int i = gtid; i < NN; i += gsz) dinv[i] = rsqrtf(deg[i]);
    }
    grid_barrier(2);

    // ---------------- P3: scan -> offsets, cursor ----------------
    if (blockIdx.x < SCAN_BLOCKS) {
        int* sb = (int*)sh_pool;
        int* sh = sb + SCAN_TB;
        int bv = (tid < SCAN_BLOCKS) ? bsum[tid] : 0;
        sb[tid] = bv;
        __syncthreads();
        for (int off = 1; off < SCAN_TB; off <<= 1) {
            int u = (tid >= off) ? sb[tid - off] : 0;
            __syncthreads();
            sb[tid] += u;
            __syncthreads();
        }
        int blockPrefix = (blockIdx.x == 0) ? 0 : sb[blockIdx.x - 1];
        if (blockIdx.x == 0 && tid == 0) offsets[NN] = sb[SCAN_BLOCKS - 1];

        int i = blockIdx.x * SCAN_TB + tid;
        int v = (i < NN) ? counts[i] : 0;
        sh[tid] = v;
        __syncthreads();
        for (int off = 1; off < SCAN_TB; off <<= 1) {
            int u = (tid >= off) ? sh[tid - off] : 0;
            __syncthreads();
            sh[tid] += u;
            __syncthreads();
        }
        if (i < NN) {
            int excl = blockPrefix + sh[tid] - v;
            offsets[i] = excl;
            cursor[i]  = excl;
        }
    }
    grid_barrier(3);

    // ---------------- P4: fill CSR ----------------
    {
        int is64 = flags[0];
        for (int e = gtid; e < NE; e += gsz) {
            int r = load_idx(ei, e, is64);
            int c = load_idx(ei, (long long)NE + e, is64);
            if ((unsigned)r < NN && (unsigned)c < NN) {
                int pos = atomicAdd(&cursor[c], 1);
                if ((unsigned)pos < NE) {
                    float w = ew[e];
                    ps[pos] = make_int2(r, __float_as_int(dinv[r] * w * dinv[c]));
                    pl[pos] = make_int2(r, __float_as_int(w));
                }
            }
        }
    }
}

// ---------------- 40-wide propagate (exact R10/R11 body) ----------
template <bool SELF, bool BIAS>
__device__ __forceinline__ void prop40(int n, int lane,
                                       const float* __restrict__ in,
                                       float* __restrict__ out,
                                       const float* __restrict__ dinv,
                                       const float* __restrict__ bias,
                                       const int* __restrict__ offsets,
                                       const int2* __restrict__ pr) {
    int grp = lane / 10;
    int sub = lane - grp * 10;
    bool active = (lane < 30);
    float4 acc = make_float4(0.f, 0.f, 0.f, 0.f);
    int beg = offsets[n], end = offsets[n + 1];
    int e = beg;
    for (; e + 6 <= end; e += 6) {
        int2 pa, pb;
        float wa = 0.f, wb = 0.f; int sa = 0, sb = 0;
        if (active) {
            pa = pr[e + grp];     sa = pa.x; wa = __int_as_float(pa.y);
            pb = pr[e + 3 + grp]; sb = pb.x; wb = __int_as_float(pb.y);
        }
        float4 va = make_float4(0.f,0.f,0.f,0.f), vb = va;
        if (wa != 0.f) va = ((const float4*)(in + (size_t)sa * NC))[sub];
        if (wb != 0.f) vb = ((const float4*)(in + (size_t)sb * NC))[sub];
        acc.x += wa * va.x + wb * vb.x;
        acc.y += wa * va.y + wb * vb.y;
        acc.z += wa * va.z + wb * vb.z;
        acc.w += wa * va.w + wb * vb.w;
    }
    for (; e < end; e += 3) {
        int idx = e + grp;
        float w = 0.f; int s = 0;
        if (active && idx < end) {
            int2 p = pr[idx]; s = p.x; w = __int_as_float(p.y);
        }
        if (w != 0.f) {
            float4 v = ((const float4*)(in + (size_t)s * NC))[sub];
            acc.x += w * v.x; acc.y += w * v.y; acc.z += w * v.z; acc.w += w * v.w;
        }
    }
    unsigned m = 0xFFFFFFFFu;
    float t1, t2;
    t1 = __shfl_sync(m, acc.x, lane + 10); t2 = __shfl_sync(m, acc.x, lane + 20);
    acc.x += t1 + t2;
    t1 = __shfl_sync(m, acc.y, lane + 10); t2 = __shfl_sync(m, acc.y, lane + 20);
    acc.y += t1 + t2;
    t1 = __shfl_sync(m, acc.z, lane + 10); t2 = __shfl_sync(m, acc.z, lane + 20);
    acc.z += t1 + t2;
    t1 = __shfl_sync(m, acc.w, lane + 10); t2 = __shfl_sync(m, acc.w, lane + 20);
    acc.w += t1 + t2;

    if (lane < 10) {
        if (SELF) {
            float dii = dinv[n]; dii *= dii;
            float4 v = ((const float4*)(in + (size_t)n * NC))[lane];
            acc.x += dii * v.x; acc.y += dii * v.y;
            acc.z += dii * v.z; acc.w += dii * v.w;
        }
        if (BIAS) {
            float4 bb = ((const float4*)bias)[lane];
            acc.x += bb.x; acc.y += bb.y; acc.z += bb.z; acc.w += bb.w;
        }
        ((float4*)(out + (size_t)n * NC))[lane] = acc;
    }
}

#define PROP_BLOCKS ((NN + 7) / 8)    // 6250 blocks per role

// ---------------- LPA iter1 as label histogram (no one-hot gather) ----------
// out[n][c] = sum_{e->n, mask[src]} w_e * (y[src]==c). Per-warp 40-slot shared
// histogram; classes spread -> near-conflict-free shared atomics.
__device__ __forceinline__ void lpa1_body(int n, int lane, int wib,
                                          float* __restrict__ hist,  // 40 floats
                                          float* __restrict__ out,
                                          const int* __restrict__ offsets,
                                          const int2* __restrict__ pl,
                                          const void* __restrict__ y,
                                          const void* __restrict__ mask,
                                          int y64, int m4) {
    for (int i = lane; i < NC; i += 32) hist[i] = 0.0f;
    __syncwarp();
    int beg = offsets[n], end = offsets[n + 1];
    for (int base = beg; base < end; base += 32) {
        int e = base + lane;
        if (e < end) {
            int2 p = pl[e];
            int src = p.x;
            int mv = m4 ? ((const int*)mask)[src]
                        : (int)((const unsigned char*)mask)[src];
            if (mv != 0) {
                int yv = load_idx(y, src, y64);
                if ((unsigned)yv < NC)
                    atomicAdd(&hist[yv], __int_as_float(p.y));
            }
        }
    }
    __syncwarp();
    if (lane < 10)
        ((float4*)(out + (size_t)n * NC))[lane] = ((const float4*)hist)[lane];
}

// K1: even blocks = SGC hop1 (z0->z1), odd blocks = LPA iter1 (labels -> l1)
__global__ __launch_bounds__(256) void k1_kernel(
        const float* __restrict__ z0, float* __restrict__ z1,
        float* __restrict__ l1,
        const float* __restrict__ dinv,
        const int* __restrict__ offsets,
        const int2* __restrict__ ps, const int2* __restrict__ pl,
        const void* __restrict__ y, const void* __restrict__ mask,
        const int* __restrict__ flags) {
    __shared__ float hist[8 * NC];
    int lane = threadIdx.x & 31;
    int wib  = threadIdx.x >> 5;
    int role = blockIdx.x & 1;
    int n = (blockIdx.x >> 1) * 8 + wib;
    if (n >= NN) return;
    if (role == 0) {
        prop40<true, false>(n, lane, z0, z1, dinv, nullptr, offsets, ps);
    } else {
        lpa1_body(n, lane, wib, &hist[wib * NC], l1, offsets, pl,
                  y, mask, flags[2], flags[1]);
    }
}

// K2: even = SGC hop2 (+bias -> x_out), odd = LPA iter2 (l1 -> l0)
__global__ __launch_bounds__(256) void k2_kernel(
        const float* __restrict__ z1, float* __restrict__ x_out,
        const float* __restrict__ l1, float* __restrict__ l0,
        const float* __restrict__ dinv, const float* __restrict__ bias,
        const int* __restrict__ offsets,
        const int2* __restrict__ ps, const int2* __restrict__ pl) {
    int lane = threadIdx.x & 31;
    int wib  = threadIdx.x >> 5;
    int role = blockIdx.x & 1;
    int n = (blockIdx.x >> 1) * 8 + wib;
    if (n >= NN) return;
    if (role == 0) {
        prop40<true, true>(n, lane, z1, x_out, dinv, bias, offsets, ps);
    } else {
        prop40<false, false>(n, lane, l1, l0, dinv, bias, offsets, pl);
    }
}

__global__ __launch_bounds__(256) void lpa_final_kernel(
        const float* __restrict__ in, float* __restrict__ out,
        const int* __restrict__ offsets, const int2* __restrict__ pl) {
    int lane = threadIdx.x & 31;
    int n = blockIdx.x * 8 + (threadIdx.x >> 5);
    if (n < NN) prop40<false, false>(n, lane, in, out, nullptr, nullptr, offsets, pl);
}

// ---------------- launch ----------------

extern "C" void kernel_launch(void* const* d_in, const int* in_sizes, int n_in,
                              void* d_out, int out_size) {
    const float* x    = (const float*)d_in[0];
    const void*  ei   = d_in[1];
    const void*  y    = d_in[2];
    const void*  mask = d_in[3];
    const float* ew   = (const float*)d_in[4];
    const float* W    = (const float*)d_in[5];
    const float* b    = (const float*)d_in[6];
    float* out = (float*)d_out;
    float* x_out   = out;
    float* lpa_out = out + NN * NC;

    static float* s = nullptr;
    if (s == nullptr) {
        void* p = nullptr;
        cudaGetSymbolAddress(&p, g_scratch);
        s = (float*)p;
    }
    float* deg     = s + OFF_DEG;
    float* dinv    = s + OFF_DINV;
    int*   counts  = (int*)(s + OFF_COUNTS);
    int*   cursor  = (int*)(s + OFF_CURSOR);
    int*   offsets = (int*)(s + OFF_OFFSETS);
    int*   flags   = (int*)(s + OFF_FLAGS);
    int*   bsum    = (int*)(s + OFF_BSUM);
    int2*  ps      = (int2*)(s + OFF_PAIR_SGC);
    int2*  pl      = (int2*)(s + OFF_PAIR_LPA);
    float* z0      = s + OFF_Z0;
    float* z1      = s + OFF_Z1;
    float* l0      = s + OFF_L0;
    float* l1      = s + OFF_L1;

    // K0: CSR build + sniff + gemm (R11 form)
    build_kernel<<<BUILD_GRID, BUILD_TB>>>(
        deg, counts, flags, bsum, offsets, cursor, dinv,
        ps, pl, z0, ei, y, mask, ew, x, W);

    // K1: SGC hop1 + LPA iter1 (label histogram — no one-hot buffer)
    k1_kernel<<<2 * PROP_BLOCKS, 256>>>(
        z0, z1, l1, dinv, offsets, ps, pl, y, mask, flags);
    // K2: SGC hop2 (+bias -> x_out) + LPA iter2
    k2_kernel<<<2 * PROP_BLOCKS, 256>>>(
        z1, x_out, l1, l0, dinv, b, offsets, ps, pl);
    // K3: LPA iter3 -> lpa_out
    lpa_final_kernel<<<PROP_BLOCKS, 256>>>(l0, lpa_out, offsets, pl);

    (void)in_sizes; (void)n_in; (void)out_size;
}